// round 1
// baseline (speedup 1.0000x reference)
#include <cuda_runtime.h>
#include <math.h>

// Problem constants
#define B_SZ   2048
#define C_SZ   64
#define D_SZ   1024
#define KACT   4
#define INV_TEMP (1.0f/0.07f)
#define MARGIN_C 0.15f

__device__ float g_partial[B_SZ];

__global__ __launch_bounds__(256, 4)
void loss_kernel(const float* __restrict__ pred,
                 const int*   __restrict__ labels,
                 const float* __restrict__ emb,
                 const float* __restrict__ cpos,
                 const float* __restrict__ conn)
{
    __shared__ float s_act_emb[4][1024];   // 16 KB: active embedding rows
    __shared__ float s_W[64][65];          // padded: conflict-free row reads
    __shared__ float s_pred[64];
    __shared__ int   s_lab[64];
    __shared__ float s_pos[64*3];
    __shared__ int   s_act[4];
    __shared__ int   s_inact[60];
    __shared__ float s_dot[4][64];
    __shared__ float s_norm[64];
    __shared__ float s_rn[64];
    __shared__ float s_bce[64], s_pl[64], s_sp[64], s_nw[64], s_m[64];

    const int b   = blockIdx.x;
    const int tid = threadIdx.x;

    // ---------------- Phase A: scalars + W/positions into SMEM ----------------
    if (tid < 64) { s_pred[tid] = pred[b*64 + tid]; s_lab[tid] = labels[b*64 + tid]; }
    if (tid < 192) s_pos[tid] = cpos[tid];
    for (int i = tid; i < 4096; i += 256) s_W[i >> 6][i & 63] = conn[i];
    __syncthreads();

    float topk_b = 0.0f;
    if (tid == 0) {
        int na = 0, ni = 0;
        for (int c = 0; c < 64; ++c) {
            if (s_lab[c]) s_act[na++] = c; else s_inact[ni++] = c;
        }
        // top-4 of pred (ties -> lowest index, like lax.top_k)
        int t0, t1, t2, t3; float bv; int bi;
        bv = -1e30f; bi = 0; for (int c = 0; c < 64; ++c){ float v = s_pred[c]; if (v > bv){bv=v;bi=c;} } t0 = bi;
        bv = -1e30f; bi = 0; for (int c = 0; c < 64; ++c){ if (c==t0) continue; float v = s_pred[c]; if (v > bv){bv=v;bi=c;} } t1 = bi;
        bv = -1e30f; bi = 0; for (int c = 0; c < 64; ++c){ if (c==t0||c==t1) continue; float v = s_pred[c]; if (v > bv){bv=v;bi=c;} } t2 = bi;
        bv = -1e30f; bi = 0; for (int c = 0; c < 64; ++c){ if (c==t0||c==t1||c==t2) continue; float v = s_pred[c]; if (v > bv){bv=v;bi=c;} } t3 = bi;
        int inter = (s_lab[t0]!=0) + (s_lab[t1]!=0) + (s_lab[t2]!=0) + (s_lab[t3]!=0);
        float un = (float)(8 - inter);            // |union| = 4+4-inter
        topk_b = 1.0f - (float)inter / (un + 1e-8f);
    }
    __syncthreads();

    // ---------------- Phase B: stage the 4 active rows in SMEM ----------------
    {
        const float4* base = (const float4*)(emb + (size_t)b * 65536);
        for (int f = tid; f < 1024; f += 256) {
            int k = f >> 8, w = f & 255;
            ((float4*)s_act_emb[k])[w] = base[(size_t)s_act[k] * 256 + w];
        }
    }
    __syncthreads();

    // ---------------- Phase C: stream all 64 rows, 2 rows/warp-pass ----------------
    {
        const int w = tid >> 5, lane = tid & 31;
        const float4* a0 = (const float4*)s_act_emb[0];
        const float4* a1 = (const float4*)s_act_emb[1];
        const float4* a2 = (const float4*)s_act_emb[2];
        const float4* a3 = (const float4*)s_act_emb[3];
        for (int pass = 0; pass < 4; ++pass) {
            const int j0 = w * 8 + pass * 2;
            const float4* r0 = (const float4*)(emb + (size_t)b * 65536 + (size_t)j0 * 1024);
            const float4* r1 = r0 + 256;
            float d00=0.f,d01=0.f,d02=0.f,d03=0.f,n0=0.f;
            float d10=0.f,d11=0.f,d12=0.f,d13=0.f,n1=0.f;
            #pragma unroll
            for (int ii = 0; ii < 8; ++ii) {
                const int i = lane + ii * 32;
                float4 e0 = r0[i]; float4 e1 = r1[i];
                float4 v0 = a0[i]; float4 v1 = a1[i]; float4 v2 = a2[i]; float4 v3 = a3[i];
                d00 = fmaf(e0.x,v0.x, fmaf(e0.y,v0.y, fmaf(e0.z,v0.z, fmaf(e0.w,v0.w, d00))));
                d01 = fmaf(e0.x,v1.x, fmaf(e0.y,v1.y, fmaf(e0.z,v1.z, fmaf(e0.w,v1.w, d01))));
                d02 = fmaf(e0.x,v2.x, fmaf(e0.y,v2.y, fmaf(e0.z,v2.z, fmaf(e0.w,v2.w, d02))));
                d03 = fmaf(e0.x,v3.x, fmaf(e0.y,v3.y, fmaf(e0.z,v3.z, fmaf(e0.w,v3.w, d03))));
                n0  = fmaf(e0.x,e0.x, fmaf(e0.y,e0.y, fmaf(e0.z,e0.z, fmaf(e0.w,e0.w, n0 ))));
                d10 = fmaf(e1.x,v0.x, fmaf(e1.y,v0.y, fmaf(e1.z,v0.z, fmaf(e1.w,v0.w, d10))));
                d11 = fmaf(e1.x,v1.x, fmaf(e1.y,v1.y, fmaf(e1.z,v1.z, fmaf(e1.w,v1.w, d11))));
                d12 = fmaf(e1.x,v2.x, fmaf(e1.y,v2.y, fmaf(e1.z,v2.z, fmaf(e1.w,v2.w, d12))));
                d13 = fmaf(e1.x,v3.x, fmaf(e1.y,v3.y, fmaf(e1.z,v3.z, fmaf(e1.w,v3.w, d13))));
                n1  = fmaf(e1.x,e1.x, fmaf(e1.y,e1.y, fmaf(e1.z,e1.z, fmaf(e1.w,e1.w, n1 ))));
            }
            #pragma unroll
            for (int off = 16; off; off >>= 1) {
                d00 += __shfl_down_sync(0xffffffffu, d00, off);
                d01 += __shfl_down_sync(0xffffffffu, d01, off);
                d02 += __shfl_down_sync(0xffffffffu, d02, off);
                d03 += __shfl_down_sync(0xffffffffu, d03, off);
                n0  += __shfl_down_sync(0xffffffffu, n0 , off);
                d10 += __shfl_down_sync(0xffffffffu, d10, off);
                d11 += __shfl_down_sync(0xffffffffu, d11, off);
                d12 += __shfl_down_sync(0xffffffffu, d12, off);
                d13 += __shfl_down_sync(0xffffffffu, d13, off);
                n1  += __shfl_down_sync(0xffffffffu, n1 , off);
            }
            if (lane == 0) {
                s_dot[0][j0] = d00; s_dot[1][j0] = d01; s_dot[2][j0] = d02; s_dot[3][j0] = d03; s_norm[j0] = n0;
                s_dot[0][j0+1]=d10; s_dot[1][j0+1]=d11; s_dot[2][j0+1]=d12; s_dot[3][j0+1]=d13; s_norm[j0+1]=n1;
            }
        }
    }
    __syncthreads();

    // ---------------- Phase D: finish all loss terms ----------------
    if (tid < 64) s_rn[tid] = 1.0f / fmaxf(sqrtf(s_norm[tid]), 1e-12f);
    __syncthreads();

    // Contrastive: 12 anchor-positive pairs. For pair p: k = p/3, the 20
    // negatives are sim_ai[k][20*(p%3) .. +19] (flat reshape aligns on 20|60).
    float ce = 0.0f;
    if (tid < 12) {
        const int p  = tid;
        const int k  = p / 3;
        const int jo = p % 3;
        const int col = jo + (jo >= k ? 1 : 0);
        const int ck = s_act[k];
        const int cj = s_act[col];
        const float rk = s_rn[ck];
        const float l0 = s_dot[k][cj] * rk * s_rn[cj] * INV_TEMP;
        const int base = 20 * jo;
        float mx = l0;
        #pragma unroll
        for (int n = 0; n < 20; ++n) {
            int c = s_inact[base + n];
            float v = s_dot[k][c] * rk * s_rn[c] * INV_TEMP;
            mx = fmaxf(mx, v);
        }
        float ssum = expf(l0 - mx);
        #pragma unroll
        for (int n = 0; n < 20; ++n) {
            int c = s_inact[base + n];
            float v = s_dot[k][c] * rk * s_rn[c] * INV_TEMP;
            ssum += expf(v - mx);
        }
        ce = logf(ssum) + mx - l0;
    }
    if (tid < 32) {                        // whole warp 0: reduce ce
        __syncwarp();
        #pragma unroll
        for (int off = 16; off; off >>= 1) ce += __shfl_down_sync(0xffffffffu, ce, off);
    }

    // Per-channel scalar terms
    if (tid < 64) {
        const int   c   = tid;
        const float p   = s_pred[c];
        const int   lab = s_lab[c];
        s_bce[c] = lab ? logf(p) : log1pf(-p);
        s_pl[c]  = lab ? p : 0.0f;
        const float mi = (p > 0.5f) ? 1.0f : 0.0f;
        s_m[c] = mi;
        float ssum = 0.0f;
        if (mi != 0.0f) {
            const float x = s_pos[c*3], y = s_pos[c*3+1], z = s_pos[c*3+2];
            for (int j = 0; j < 64; ++j) {
                if (j == c) continue;
                if (s_pred[j] > 0.5f) {
                    float dx = x - s_pos[j*3], dy = y - s_pos[j*3+1], dz = z - s_pos[j*3+2];
                    ssum += sqrtf(fmaf(dx,dx, fmaf(dy,dy, dz*dz)));
                }
            }
        }
        s_sp[c] = ssum;
        float ns = 0.0f;
        for (int j = 0; j < 64; ++j) ns = fmaf(s_W[c][j], s_pred[j], ns);
        s_nw[c] = ns * p;
    }
    __syncthreads();

    if (tid < 32) {
        float r_bce = s_bce[tid] + s_bce[tid+32];
        float r_pl  = s_pl [tid] + s_pl [tid+32];
        float r_p   = s_pred[tid] + s_pred[tid+32];
        float r_lab = (float)s_lab[tid] + (float)s_lab[tid+32];
        float r_sp  = s_sp[tid] + s_sp[tid+32];
        float r_nw  = s_nw[tid] + s_nw[tid+32];
        float r_m   = s_m [tid] + s_m [tid+32];
        #pragma unroll
        for (int off = 16; off; off >>= 1) {
            r_bce += __shfl_down_sync(0xffffffffu, r_bce, off);
            r_pl  += __shfl_down_sync(0xffffffffu, r_pl , off);
            r_p   += __shfl_down_sync(0xffffffffu, r_p  , off);
            r_lab += __shfl_down_sync(0xffffffffu, r_lab, off);
            r_sp  += __shfl_down_sync(0xffffffffu, r_sp , off);
            r_nw  += __shfl_down_sync(0xffffffffu, r_nw , off);
            r_m   += __shfl_down_sync(0xffffffffu, r_m  , off);
        }
        if (tid == 0) {
            float score_b   = -r_bce * (1.0f/64.0f);
            float act_mean   = r_pl / r_lab;
            float inact_mean = (r_p - r_pl) / (64.0f - r_lab);
            float margin_b  = fmaxf(MARGIN_C - (act_mean - inact_mean), 0.0f);
            float contr_b   = ce * (1.0f/12.0f);
            float nm        = r_m;
            float spatial_b = (nm >= 2.0f) ? r_sp / fmaxf(nm*(nm-1.0f), 1.0f) : 0.0f;
            float net_b     = -r_nw * (1.0f/4096.0f);
            g_partial[b] = 3.0f*score_b + 1.0f*margin_b + 2.0f*topk_b
                         + 1.0f*contr_b + 0.5f*spatial_b + 0.5f*net_b;
        }
    }
}

__global__ void reduce_kernel(float* __restrict__ out)
{
    __shared__ float s[1024];
    const int t = threadIdx.x;
    s[t] = g_partial[t] + g_partial[t + 1024];
    __syncthreads();
    for (int o = 512; o > 0; o >>= 1) {
        if (t < o) s[t] += s[t + o];
        __syncthreads();
    }
    if (t == 0) out[0] = s[0] * (1.0f / (float)B_SZ);
}

extern "C" void kernel_launch(void* const* d_in, const int* in_sizes, int n_in,
                              void* d_out, int out_size)
{
    const float* pred = (const float*)d_in[0];
    const int*   lab  = (const int*)  d_in[1];
    const float* emb  = (const float*)d_in[2];
    const float* cpos = (const float*)d_in[3];
    const float* conn = (const float*)d_in[4];
    loss_kernel<<<B_SZ, 256>>>(pred, lab, emb, cpos, conn);
    reduce_kernel<<<1, 1024>>>((float*)d_out);
}

// round 3
// speedup vs baseline: 1.1749x; 1.1749x over previous
#include <cuda_runtime.h>
#include <math.h>

#define B_SZ   2048
#define INV_TEMP (1.0f/0.07f)
#define MARGIN_C 0.15f

#define FMA2(d,a,b,c) asm("fma.rn.f32x2 %0, %1, %2, %3;" : "=l"(d) : "l"(a), "l"(b), "l"(c))
#define UNPACK2(lo,hi,v) asm("mov.b64 {%0, %1}, %2;" : "=f"(lo), "=f"(hi) : "l"(v))

__device__ float        g_partial[B_SZ];
__device__ unsigned int g_count = 0;

typedef unsigned long long ull;

__global__ __launch_bounds__(256, 2)
void loss_kernel(const float* __restrict__ pred,
                 const int*   __restrict__ labels,
                 const float* __restrict__ emb,
                 const float* __restrict__ cpos,
                 const float* __restrict__ conn,
                 float* __restrict__ out)
{
    __shared__ __align__(16) float s_act_emb[4][1024];   // 16 KB
    __shared__ float s_pred[64];
    __shared__ int   s_lab[64];
    __shared__ float s_pos[192];
    __shared__ int   s_act[4];
    __shared__ int   s_inact[60];
    __shared__ float s_dot[4][64];
    __shared__ float s_norm[64];
    __shared__ float s_rn[64];
    __shared__ float s_bce[64], s_pl[64], s_sp[64], s_nw[64], s_m[64];
    __shared__ int   s_islast;
    __shared__ float s_red[256];

    const int b   = blockIdx.x;
    const int tid = threadIdx.x;
    const int w   = tid >> 5, lane = tid & 31;

    // ---------------- Phase A: scalars into SMEM ----------------
    if (tid < 64) { s_pred[tid] = pred[b*64 + tid]; s_lab[tid] = labels[b*64 + tid]; }
    if (tid >= 64 && tid < 256) s_pos[tid - 64] = cpos[tid - 64];
    __syncthreads();

    float topk_b = 0.0f;
    if (tid == 0) {
        int na = 0, ni = 0;
        for (int c = 0; c < 64; ++c) {
            if (s_lab[c]) s_act[na++] = c; else s_inact[ni++] = c;
        }
        int t0, t1, t2, t3; float bv; int bi;
        bv = -1e30f; bi = 0; for (int c = 0; c < 64; ++c){ float v = s_pred[c]; if (v > bv){bv=v;bi=c;} } t0 = bi;
        bv = -1e30f; bi = 0; for (int c = 0; c < 64; ++c){ if (c==t0) continue; float v = s_pred[c]; if (v > bv){bv=v;bi=c;} } t1 = bi;
        bv = -1e30f; bi = 0; for (int c = 0; c < 64; ++c){ if (c==t0||c==t1) continue; float v = s_pred[c]; if (v > bv){bv=v;bi=c;} } t2 = bi;
        bv = -1e30f; bi = 0; for (int c = 0; c < 64; ++c){ if (c==t0||c==t1||c==t2) continue; float v = s_pred[c]; if (v > bv){bv=v;bi=c;} } t3 = bi;
        int inter = (s_lab[t0]!=0) + (s_lab[t1]!=0) + (s_lab[t2]!=0) + (s_lab[t3]!=0);
        float un = (float)(8 - inter);
        topk_b = 1.0f - (float)inter / (un + 1e-8f);
    }
    __syncthreads();

    // ---------------- Phase B: stage 4 active rows into SMEM ----------------
    {
        const float4* base = (const float4*)(emb + (size_t)b * 65536);
        for (int f = tid; f < 1024; f += 256) {
            int k = f >> 8, i = f & 255;
            ((float4*)s_act_emb[k])[i] = base[(size_t)s_act[k] * 256 + i];
        }
    }
    __syncthreads();

    // ---------------- Phase C: stream 64 rows, 4 rows/pass, f32x2 FMA ----------------
    {
        const ull zero = 0ull;
        #pragma unroll
        for (int pass = 0; pass < 2; ++pass) {
            const int j0 = w * 8 + pass * 4;
            const ulonglong2* r0 = (const ulonglong2*)(emb + (size_t)b * 65536 + (size_t)j0 * 1024);
            const ulonglong2* r1 = r0 + 256;
            const ulonglong2* r2 = r0 + 512;
            const ulonglong2* r3 = r0 + 768;
            ull d00=zero,d01=zero,d02=zero,d03=zero,n0=zero;
            ull d10=zero,d11=zero,d12=zero,d13=zero,n1=zero;
            ull d20=zero,d21=zero,d22=zero,d23=zero,n2=zero;
            ull d30=zero,d31=zero,d32=zero,d33=zero,n3=zero;
            #pragma unroll
            for (int ii = 0; ii < 8; ++ii) {
                const int i = lane + ii * 32;
                ulonglong2 e0 = r0[i], e1 = r1[i], e2 = r2[i], e3 = r3[i];
                ulonglong2 a0 = ((const ulonglong2*)s_act_emb[0])[i];
                ulonglong2 a1 = ((const ulonglong2*)s_act_emb[1])[i];
                ulonglong2 a2 = ((const ulonglong2*)s_act_emb[2])[i];
                ulonglong2 a3 = ((const ulonglong2*)s_act_emb[3])[i];
                FMA2(d00,e0.x,a0.x,d00); FMA2(d00,e0.y,a0.y,d00);
                FMA2(d01,e0.x,a1.x,d01); FMA2(d01,e0.y,a1.y,d01);
                FMA2(d02,e0.x,a2.x,d02); FMA2(d02,e0.y,a2.y,d02);
                FMA2(d03,e0.x,a3.x,d03); FMA2(d03,e0.y,a3.y,d03);
                FMA2(n0 ,e0.x,e0.x,n0 ); FMA2(n0 ,e0.y,e0.y,n0 );
                FMA2(d10,e1.x,a0.x,d10); FMA2(d10,e1.y,a0.y,d10);
                FMA2(d11,e1.x,a1.x,d11); FMA2(d11,e1.y,a1.y,d11);
                FMA2(d12,e1.x,a2.x,d12); FMA2(d12,e1.y,a2.y,d12);
                FMA2(d13,e1.x,a3.x,d13); FMA2(d13,e1.y,a3.y,d13);
                FMA2(n1 ,e1.x,e1.x,n1 ); FMA2(n1 ,e1.y,e1.y,n1 );
                FMA2(d20,e2.x,a0.x,d20); FMA2(d20,e2.y,a0.y,d20);
                FMA2(d21,e2.x,a1.x,d21); FMA2(d21,e2.y,a1.y,d21);
                FMA2(d22,e2.x,a2.x,d22); FMA2(d22,e2.y,a2.y,d22);
                FMA2(d23,e2.x,a3.x,d23); FMA2(d23,e2.y,a3.y,d23);
                FMA2(n2 ,e2.x,e2.x,n2 ); FMA2(n2 ,e2.y,e2.y,n2 );
                FMA2(d30,e3.x,a0.x,d30); FMA2(d30,e3.y,a0.y,d30);
                FMA2(d31,e3.x,a1.x,d31); FMA2(d31,e3.y,a1.y,d31);
                FMA2(d32,e3.x,a2.x,d32); FMA2(d32,e3.y,a2.y,d32);
                FMA2(d33,e3.x,a3.x,d33); FMA2(d33,e3.y,a3.y,d33);
                FMA2(n3 ,e3.x,e3.x,n3 ); FMA2(n3 ,e3.y,e3.y,n3 );
            }
            float v[20];
            {
                ull acc[20] = {d00,d01,d02,d03,n0, d10,d11,d12,d13,n1,
                               d20,d21,d22,d23,n2, d30,d31,d32,d33,n3};
                #pragma unroll
                for (int t = 0; t < 20; ++t) {
                    float lo, hi; UNPACK2(lo, hi, acc[t]);
                    v[t] = lo + hi;
                }
            }
            #pragma unroll
            for (int off = 16; off; off >>= 1) {
                #pragma unroll
                for (int t = 0; t < 20; ++t)
                    v[t] += __shfl_down_sync(0xffffffffu, v[t], off);
            }
            if (lane == 0) {
                #pragma unroll
                for (int r = 0; r < 4; ++r) {
                    s_dot[0][j0+r] = v[r*5+0];
                    s_dot[1][j0+r] = v[r*5+1];
                    s_dot[2][j0+r] = v[r*5+2];
                    s_dot[3][j0+r] = v[r*5+3];
                    s_norm[j0+r]   = v[r*5+4];
                }
            }
        }
    }
    __syncthreads();

    // ---------------- Phase D ----------------
    if (tid < 64) s_rn[tid] = 1.0f / fmaxf(sqrtf(s_norm[tid]), 1e-12f);

    // per-channel scalar terms (64 threads)
    if (tid >= 64 && tid < 128) {
        const int   c   = tid - 64;
        const float p   = s_pred[c];
        const int   lab = s_lab[c];
        s_bce[c] = lab ? logf(p) : log1pf(-p);
        s_pl[c]  = lab ? p : 0.0f;
        const float mi = (p > 0.5f) ? 1.0f : 0.0f;
        s_m[c] = mi;
        float ssum = 0.0f;
        if (mi != 0.0f) {
            const float x = s_pos[c*3], y = s_pos[c*3+1], z = s_pos[c*3+2];
            for (int j = 0; j < 64; ++j) {
                if (j == c) continue;
                if (s_pred[j] > 0.5f) {
                    float dx = x - s_pos[j*3], dy = y - s_pos[j*3+1], dz = z - s_pos[j*3+2];
                    ssum += sqrtf(fmaf(dx,dx, fmaf(dy,dy, dz*dz)));
                }
            }
        }
        s_sp[c] = ssum;
    }

    // network term: each warp handles 8 rows of conn (L2-resident, coalesced)
    {
        const float pl0 = s_pred[lane], pl1 = s_pred[lane + 32];
        #pragma unroll
        for (int rr = 0; rr < 8; ++rr) {
            const int r = w * 8 + rr;
            float t1 = fmaf(conn[r*64 + lane], pl0, conn[r*64 + 32 + lane] * pl1);
            #pragma unroll
            for (int off = 16; off; off >>= 1)
                t1 += __shfl_down_sync(0xffffffffu, t1, off);
            if (lane == 0) s_nw[r] = t1 * s_pred[r];
        }
    }
    __syncthreads();

    // contrastive: 12 pairs in warp 0; negatives for pair p are a contiguous
    // 20-slice of the inactive list (flat reshape aligns on 20|60).
    float ce = 0.0f;
    if (tid < 12) {
        const int p  = tid;
        const int k  = p / 3;
        const int jo = p % 3;
        const int col = jo + (jo >= k ? 1 : 0);
        const int ck = s_act[k];
        const int cj = s_act[col];
        const float rk = s_rn[ck];
        const float l0 = s_dot[k][cj] * rk * s_rn[cj] * INV_TEMP;
        const int base = 20 * jo;
        float mx = l0;
        #pragma unroll
        for (int n = 0; n < 20; ++n) {
            int c = s_inact[base + n];
            float vv = s_dot[k][c] * rk * s_rn[c] * INV_TEMP;
            mx = fmaxf(mx, vv);
        }
        float ssum = expf(l0 - mx);
        #pragma unroll
        for (int n = 0; n < 20; ++n) {
            int c = s_inact[base + n];
            float vv = s_dot[k][c] * rk * s_rn[c] * INV_TEMP;
            ssum += expf(vv - mx);
        }
        ce = logf(ssum) + mx - l0;
    }
    if (tid < 32) {
        #pragma unroll
        for (int off = 16; off; off >>= 1) ce += __shfl_down_sync(0xffffffffu, ce, off);
    }

    if (tid < 32) {
        float r_bce = s_bce[tid] + s_bce[tid+32];
        float r_pl  = s_pl [tid] + s_pl [tid+32];
        float r_p   = s_pred[tid] + s_pred[tid+32];
        float r_lab = (float)s_lab[tid] + (float)s_lab[tid+32];
        float r_sp  = s_sp[tid] + s_sp[tid+32];
        float r_nw  = s_nw[tid] + s_nw[tid+32];
        float r_m   = s_m [tid] + s_m [tid+32];
        #pragma unroll
        for (int off = 16; off; off >>= 1) {
            r_bce += __shfl_down_sync(0xffffffffu, r_bce, off);
            r_pl  += __shfl_down_sync(0xffffffffu, r_pl , off);
            r_p   += __shfl_down_sync(0xffffffffu, r_p  , off);
            r_lab += __shfl_down_sync(0xffffffffu, r_lab, off);
            r_sp  += __shfl_down_sync(0xffffffffu, r_sp , off);
            r_nw  += __shfl_down_sync(0xffffffffu, r_nw , off);
            r_m   += __shfl_down_sync(0xffffffffu, r_m  , off);
        }
        if (tid == 0) {
            float score_b    = -r_bce * (1.0f/64.0f);
            float act_mean   = r_pl / r_lab;
            float inact_mean = (r_p - r_pl) / (64.0f - r_lab);
            float margin_b   = fmaxf(MARGIN_C - (act_mean - inact_mean), 0.0f);
            float contr_b    = ce * (1.0f/12.0f);
            float nm         = r_m;
            float spatial_b  = (nm >= 2.0f) ? r_sp / fmaxf(nm*(nm-1.0f), 1.0f) : 0.0f;
            float net_b      = -r_nw * (1.0f/4096.0f);
            g_partial[b] = 3.0f*score_b + 1.0f*margin_b + 2.0f*topk_b
                         + 1.0f*contr_b + 0.5f*spatial_b + 0.5f*net_b;
        }
    }

    // ---------------- fused final reduction (last block) ----------------
    if (tid == 0) {
        __threadfence();
        unsigned int v = atomicAdd(&g_count, 1u);
        s_islast = (v == (unsigned)(B_SZ - 1));
    }
    __syncthreads();
    if (s_islast) {
        float s = 0.0f;
        for (int i = tid; i < B_SZ; i += blockDim.x) s += g_partial[i];
        s_red[tid] = s;
        __syncthreads();
        for (int o = 128; o > 0; o >>= 1) {
            if (tid < o) s_red[tid] += s_red[tid + o];
            __syncthreads();
        }
        if (tid == 0) { out[0] = s_red[0] * (1.0f / (float)B_SZ); g_count = 0; }
    }
}

extern "C" void kernel_launch(void* const* d_in, const int* in_sizes, int n_in,
                              void* d_out, int out_size)
{
    const float* pred = (const float*)d_in[0];
    const int*   lab  = (const int*)  d_in[1];
    const float* emb  = (const float*)d_in[2];
    const float* cpos = (const float*)d_in[3];
    const float* conn = (const float*)d_in[4];
    loss_kernel<<<B_SZ, 256>>>(pred, lab, emb, cpos, conn, (float*)d_out);
}